// round 1
// baseline (speedup 1.0000x reference)
#include <cuda_runtime.h>

#define NC   10
#define NBLK 1184
#define TPB  256

// slots 0..9  : per-class sqerr sums
// slots 10..19: per-class counts
__device__ float g_partials[2 * NC * NBLK];

__global__ __launch_bounds__(TPB) void myloss2_reduce_kernel(
    const float* __restrict__ o,
    const float* __restrict__ t,
    const int*   __restrict__ m,
    int n)
{
    float sum[NC];
    float cnt[NC];
#pragma unroll
    for (int c = 0; c < NC; c++) { sum[c] = 0.f; cnt[c] = 0.f; }

    const int nvec = n >> 2;
    const float4* __restrict__ o4 = (const float4*)o;
    const float4* __restrict__ t4 = (const float4*)t;
    const int4*   __restrict__ m4 = (const int4*)m;

    for (int i = blockIdx.x * blockDim.x + threadIdx.x; i < nvec;
         i += gridDim.x * blockDim.x) {
        float4 ov = o4[i];
        float4 tv = t4[i];
        int4   mv = m4[i];

        float os[4] = {ov.x, ov.y, ov.z, ov.w};
        float ts[4] = {tv.x, tv.y, tv.z, tv.w};
        int   ms[4] = {mv.x, mv.y, mv.z, mv.w};

#pragma unroll
        for (int e = 0; e < 4; e++) {
            float d   = os[e] - ts[e];
            float sq  = d * d;
            float vm  = (ms[e] == 1) ? 1.0f : 0.0f;
            float sqm = sq * vm;
            int   cls = (int)ts[e];
#pragma unroll
            for (int c = 0; c < NC; c++) {
                bool p = (cls == c);
                sum[c] += p ? sqm : 0.0f;
                cnt[c] += p ? vm  : 0.0f;
            }
        }
    }

    // scalar tail (N % 4 != 0 — not hit for this shape, kept for safety)
    if (blockIdx.x == 0 && threadIdx.x == 0) {
        for (int i = (nvec << 2); i < n; i++) {
            float d  = o[i] - t[i];
            float sq = d * d;
            float vm = (m[i] == 1) ? 1.0f : 0.0f;
            int cls  = (int)t[i];
#pragma unroll
            for (int c = 0; c < NC; c++) {
                bool p = (cls == c);
                sum[c] += p ? sq * vm : 0.0f;
                cnt[c] += p ? vm      : 0.0f;
            }
        }
    }

    // warp reduce
    const unsigned full = 0xffffffffu;
#pragma unroll
    for (int c = 0; c < NC; c++) {
#pragma unroll
        for (int off = 16; off; off >>= 1) {
            sum[c] += __shfl_down_sync(full, sum[c], off);
            cnt[c] += __shfl_down_sync(full, cnt[c], off);
        }
    }

    __shared__ float sh[2 * NC][TPB / 32];
    int wid = threadIdx.x >> 5;
    int lid = threadIdx.x & 31;
    if (lid == 0) {
#pragma unroll
        for (int c = 0; c < NC; c++) {
            sh[c][wid]      = sum[c];
            sh[NC + c][wid] = cnt[c];
        }
    }
    __syncthreads();

    if (threadIdx.x < 2 * NC) {
        float a = 0.f;
#pragma unroll
        for (int w = 0; w < TPB / 32; w++) a += sh[threadIdx.x][w];
        g_partials[threadIdx.x * NBLK + blockIdx.x] = a;  // deterministic write
    }
}

__global__ void myloss2_finalize_kernel(float* __restrict__ out)
{
    // 20 warps: warp w reduces slot w across NBLK partials (coalesced).
    int w   = threadIdx.x >> 5;
    int lid = threadIdx.x & 31;
    __shared__ float red[2 * NC];

    if (w < 2 * NC) {
        float a = 0.f;
        for (int b = lid; b < NBLK; b += 32)
            a += g_partials[w * NBLK + b];
#pragma unroll
        for (int off = 16; off; off >>= 1)
            a += __shfl_down_sync(0xffffffffu, a, off);
        if (lid == 0) red[w] = a;
    }
    __syncthreads();

    if (threadIdx.x == 0) {
        float loss = 0.f;
#pragma unroll
        for (int c = 0; c < NC; c++) {
            float s  = red[c];
            float nn = red[NC + c];
            float le = (nn > 0.f) ? s / fmaxf(nn, 1.0f) : 0.0f;
            out[1 + c]  = le;   // loss_each
            out[11 + c] = nn;   // class_n
            loss += 0.1f * le;
        }
        out[0] = loss;
    }
}

extern "C" void kernel_launch(void* const* d_in, const int* in_sizes, int n_in,
                              void* d_out, int out_size)
{
    const float* o = (const float*)d_in[0];
    const float* t = (const float*)d_in[1];
    const int*   m = (const int*)d_in[2];
    float* out = (float*)d_out;
    int n = in_sizes[0];

    myloss2_reduce_kernel<<<NBLK, TPB>>>(o, t, m, n);
    myloss2_finalize_kernel<<<1, 2 * NC * 32>>>(out);
}